// round 3
// baseline (speedup 1.0000x reference)
#include <cuda_runtime.h>

// clip(x + noise, 0, 1) over 50,331,648 fp32 elements.
// Pure HBM stream: 604 MB traffic, ~6.7 TB/s achieved.
// R2: single-wave persistent grid (148 SMs x 8 CTAs) to eliminate ~4 wave
// transitions; keep .cs streaming hints + unroll-4 load batching.

#define UNROLL 4

__global__ void __launch_bounds__(256)
gauss_noise_kernel(const float4* __restrict__ x,
                   const float4* __restrict__ n,
                   float4* __restrict__ out,
                   int nvec) {
    const int tid = blockIdx.x * blockDim.x + threadIdx.x;
    const int stride = gridDim.x * blockDim.x;

    int i = tid;
    const int batch_span = stride * UNROLL;
    for (; i + stride * (UNROLL - 1) < nvec; i += batch_span) {
        float4 a[UNROLL], b[UNROLL];
#pragma unroll
        for (int u = 0; u < UNROLL; u++) a[u] = __ldcs(&x[i + u * stride]);
#pragma unroll
        for (int u = 0; u < UNROLL; u++) b[u] = __ldcs(&n[i + u * stride]);
#pragma unroll
        for (int u = 0; u < UNROLL; u++) {
            float4 r;
            r.x = __saturatef(a[u].x + b[u].x);
            r.y = __saturatef(a[u].y + b[u].y);
            r.z = __saturatef(a[u].z + b[u].z);
            r.w = __saturatef(a[u].w + b[u].w);
            __stcs(&out[i + u * stride], r);
        }
    }
    // Tail
    for (; i < nvec; i += stride) {
        float4 a = __ldcs(&x[i]);
        float4 b = __ldcs(&n[i]);
        float4 r;
        r.x = __saturatef(a.x + b.x);
        r.y = __saturatef(a.y + b.y);
        r.z = __saturatef(a.z + b.z);
        r.w = __saturatef(a.w + b.w);
        __stcs(&out[i], r);
    }
}

extern "C" void kernel_launch(void* const* d_in, const int* in_sizes, int n_in,
                              void* d_out, int out_size) {
    const float4* x = (const float4*)d_in[0];
    const float4* n = (const float4*)d_in[1];
    float4* out = (float4*)d_out;

    int nvec = in_sizes[0] / 4;  // 12,582,912
    const int threads = 256;
    // Single wave: 148 SMs x 8 resident CTAs @ 256 threads (2048 thr/SM).
    // Each thread loops ~41 float4s (~10 unroll-4 batches) — no wave
    // transitions, DRAM pipe saturated end-to-end.
    int blocks = 148 * 8;  // 1184
    gauss_noise_kernel<<<blocks, threads>>>(x, n, out, nvec);
}

// round 4
// speedup vs baseline: 1.1049x; 1.1049x over previous
#include <cuda_runtime.h>

// clip(x + noise, 0, 1) over 50,331,648 fp32 = 12,582,912 float4.
// R3: exact-cover, loop-free kernel. 12288 CTAs x 256 thr x 4 vec4 each.
// 8 front-batched LDG.128 + 4 STG.128 per thread, .cs streaming hints,
// max CTA count for fine-grained scheduler load balancing.

#define UNROLL 4

__global__ void __launch_bounds__(256)
gauss_noise_kernel(const float4* __restrict__ x,
                   const float4* __restrict__ n,
                   float4* __restrict__ out) {
    const int tid = blockIdx.x * blockDim.x + threadIdx.x;
    const int stride = gridDim.x * blockDim.x;  // 3,145,728

    float4 a[UNROLL], b[UNROLL];
#pragma unroll
    for (int u = 0; u < UNROLL; u++) a[u] = __ldcs(&x[tid + u * stride]);
#pragma unroll
    for (int u = 0; u < UNROLL; u++) b[u] = __ldcs(&n[tid + u * stride]);
#pragma unroll
    for (int u = 0; u < UNROLL; u++) {
        float4 r;
        r.x = __saturatef(a[u].x + b[u].x);
        r.y = __saturatef(a[u].y + b[u].y);
        r.z = __saturatef(a[u].z + b[u].z);
        r.w = __saturatef(a[u].w + b[u].w);
        __stcs(&out[tid + u * stride], r);
    }
}

// Fallback for sizes that don't exactly match (defensive; not expected here).
__global__ void __launch_bounds__(256)
gauss_noise_tail(const float4* __restrict__ x,
                 const float4* __restrict__ n,
                 float4* __restrict__ out,
                 int start, int nvec) {
    int i = start + blockIdx.x * blockDim.x + threadIdx.x;
    if (i < nvec) {
        float4 a = __ldcs(&x[i]);
        float4 b = __ldcs(&n[i]);
        float4 r;
        r.x = __saturatef(a.x + b.x);
        r.y = __saturatef(a.y + b.y);
        r.z = __saturatef(a.z + b.z);
        r.w = __saturatef(a.w + b.w);
        __stcs(&out[i], r);
    }
}

extern "C" void kernel_launch(void* const* d_in, const int* in_sizes, int n_in,
                              void* d_out, int out_size) {
    const float4* x = (const float4*)d_in[0];
    const float4* n = (const float4*)d_in[1];
    float4* out = (float4*)d_out;

    int nvec = in_sizes[0] / 4;  // 12,582,912
    const int threads = 256;
    int main_vec = nvec / (threads * UNROLL) * (threads * UNROLL);
    int blocks = main_vec / (threads * UNROLL);  // 12288 for this shape
    if (blocks > 0)
        gauss_noise_kernel<<<blocks, threads>>>(x, n, out);
    int rem = nvec - main_vec;
    if (rem > 0)
        gauss_noise_tail<<<(rem + threads - 1) / threads, threads>>>(x, n, out, main_vec, nvec);
}